// round 16
// baseline (speedup 1.0000x reference)
#include <cuda_runtime.h>
#include <cuda_fp16.h>
#include <math.h>
#include <stdint.h>

#define NR 1000000
#define DD 256
#define BS 4096
#define NTILES (NR / 64)

// ---------------- scratch (device globals: no allocations allowed) ----------
__device__ float g_s[NR];          // raw scores
__device__ float g_pooled[BS * DD];
__device__ int   g_is64;           // batch dtype flag: 1 = int64, 0 = int32
// W1 as fp16, transposed to [n][k] (K contiguous per output column)
__device__ __align__(16) __half g_Bh16[DD * DD];
// x converted to fp16 by score kernel (side product); read by pool2
__device__ __align__(16) __half g_x16[(size_t)NR * DD];

__device__ __forceinline__ int getb(const void* p, int i, int is64) {
    if (is64) return (int)((const long long*)p)[i];
    return ((const int*)p)[i];
}

__device__ __forceinline__ uint32_t smem_u32(const void* p) {
    uint32_t a;
    asm("{ .reg .u64 t; cvta.to.shared.u64 t, %1; cvt.u32.u64 %0, t; }"
        : "=r"(a) : "l"(p));
    return a;
}
__device__ __forceinline__ void ldm_x4(uint32_t* r, uint32_t addr) {
    asm volatile("ldmatrix.sync.aligned.m8n8.x4.shared.b16 {%0,%1,%2,%3}, [%4];"
        : "=r"(r[0]), "=r"(r[1]), "=r"(r[2]), "=r"(r[3]) : "r"(addr));
}
__device__ __forceinline__ void mma_f16(float* d, const uint32_t* a,
                                        const uint32_t* b) {
    asm volatile(
        "mma.sync.aligned.m16n8k16.row.col.f32.f16.f16.f32 "
        "{%0,%1,%2,%3}, {%4,%5,%6,%7}, {%8,%9}, {%0,%1,%2,%3};"
        : "+f"(d[0]), "+f"(d[1]), "+f"(d[2]), "+f"(d[3])
        : "r"(a[0]), "r"(a[1]), "r"(a[2]), "r"(a[3]), "r"(b[0]), "r"(b[1]));
}
__device__ __forceinline__ void cpasync16(uint32_t dst, const void* src) {
    asm volatile("cp.async.cg.shared.global [%0], [%1], 16;"
                 :: "r"(dst), "l"(src) : "memory");
}
#define CP_COMMIT() asm volatile("cp.async.commit_group;" ::: "memory")
#define CP_WAIT0()  asm volatile("cp.async.wait_group 0;" ::: "memory")

// HW tanh approximation (MUFU.TANH, sm_75+)
__device__ __forceinline__ float tanh_hw(float v) {
    float r;
    asm("tanh.approx.f32 %0, %1;" : "=f"(r) : "f"(v));
    return r;
}

// ---------------- init: detect batch dtype only -----------------------------
__global__ void init_kernel(const void* batch) {
    if (threadIdx.x == 0 && blockIdx.x == 0) {
        long long v = ((const long long*)batch)[NR / 2 - 1];
        g_is64 = (v >= 0 && v < BS) ? 1 : 0;
    }
}

// ---------------- prep: W1 -> fp16, transpose to [n][k] ---------------------
__global__ void prep_w1_kernel(const float* __restrict__ W1) {
    int i = blockIdx.x * blockDim.x + threadIdx.x;
    if (i >= DD * DD) return;
    int k = i >> 8, n = i & 255;                     // W1[k][n]
    g_Bh16[n * DD + k] = __float2half_rn(W1[i]);
}

// ---------------- dummy: keeps score at 4th launch (ncu window) -------------
__global__ void dummy_kernel() {}

// ---------------- score GEMM: persistent, single-pass fp16, 2 CTAs/SM -------
// Each CTA grid-strides over M-tiles of 64 rows; the cp.async/LDG pipeline
// never drains across tiles (next tile's chunk 0 prefetched under the last
// chunk + epilogue). Buffer parity is tile-invariant (4 chunks = even).
#define APITCH 144
#define BUFSZ  46080
#define OF_A   0
#define OF_B   9216
#define OF_RED (2 * BUFSZ)
#define SC_SMEM (2 * BUFSZ + 1024)
__global__ __launch_bounds__(256, 2)
void score_mma_kernel(const float* __restrict__ x, const float* __restrict__ b1,
                      const float* __restrict__ w2, const float* __restrict__ b2p) {
    extern __shared__ char smem[];
    const uint32_t sb = smem_u32(smem);
    const int tid = threadIdx.x;
    const int wid = tid >> 5, lane = tid & 31;
    const int mw = wid & 1;          // M warp: rows mw*32 .. +31
    const int nw = wid >> 1;         // N warp: cols nw*64 .. +63
    const float b2v = __ldg(b2p);

    const int a_row_in = (lane & 15);
    const int a_k_in   = (lane & 16) >> 1;
    const int b_n_in   = (lane & 7) + ((lane & 16) >> 1);
    const int b_k_in   = (lane & 8);

    auto loadB = [&](int c, int buf) {
        uint32_t base = sb + buf * BUFSZ;
#pragma unroll
        for (int t = 0; t < 8; t++) {
            int idx = tid + t * 256;             // 0..2047
            int n = idx >> 3, q = idx & 7;
            uint32_t doff = (uint32_t)n * APITCH + (uint32_t)q * 16;
            size_t gsrc = (size_t)n * DD + c * 64 + q * 8;
            cpasync16(base + OF_B + doff, g_Bh16 + gsrc);
        }
        CP_COMMIT();
    };
    auto loadA = [&](int bm, int c, float4* st) {
#pragma unroll
        for (int t = 0; t < 4; t++) {
            int idx = tid + t * 256;             // 0..1023 float4s
            int r = idx >> 4, q = idx & 15;
            st[t] = *(const float4*)(x + (size_t)(bm + r) * DD + c * 64 + q * 4);
        }
    };
    auto storeA = [&](const float4* st, int buf, int bm, int c) {
        char* base = smem + buf * BUFSZ;
#pragma unroll
        for (int t = 0; t < 4; t++) {
            int idx = tid + t * 256;
            int r = idx >> 4, q = idx & 15;
            __half2 h0 = __floats2half2_rn(st[t].x, st[t].y);
            __half2 h1 = __floats2half2_rn(st[t].z, st[t].w);
            uint2 hp = make_uint2(*(uint32_t*)&h0, *(uint32_t*)&h1);
            uint32_t off = (uint32_t)r * APITCH + (uint32_t)q * 8;
            *(uint2*)(base + OF_A + off) = hp;
            __stcs((uint2*)(g_x16 + (size_t)(bm + r) * DD + c * 64 + q * 4), hp);
        }
    };

    // ---- prologue for first tile ----
    float4 st[4];
    int tile = blockIdx.x;
    if (tile >= NTILES) return;
    loadB(0, 0);
    loadA(tile * 64, 0, st);
    storeA(st, 0, tile * 64, 0);
    CP_WAIT0();
    __syncthreads();

#pragma unroll 1
    for (; tile < NTILES; tile += gridDim.x) {
        const int bm = tile * 64;
        const int ntile = tile + gridDim.x;
        const bool has_next = (ntile < NTILES);

        float acc[2][8][4];
#pragma unroll
        for (int a = 0; a < 2; a++)
#pragma unroll
            for (int b = 0; b < 8; b++)
#pragma unroll
                for (int c = 0; c < 4; c++) acc[a][b][c] = 0.f;

#pragma unroll 1
        for (int c = 0; c < 4; c++) {
            const int cur = c & 1, nxt = cur ^ 1;
            if (c < 3) {
                loadB(c + 1, nxt);           // overlaps MMA burst
                loadA(bm, c + 1, st);
            } else if (has_next) {
                loadB(0, nxt);               // prefetch next tile's chunk 0
                loadA(ntile * 64, 0, st);
            }
            // ---- compute on buf[cur]: 4 k16 steps (static order) ----
            const uint32_t abase = sb + (uint32_t)cur * BUFSZ;
#pragma unroll
            for (int ks = 0; ks < 4; ks++) {
                const int k0 = ks * 16;
                uint32_t ah[2][4];
#pragma unroll
                for (int mt = 0; mt < 2; mt++) {
                    uint32_t row = (uint32_t)(mw * 32 + mt * 16 + a_row_in);
                    uint32_t col = (uint32_t)(k0 + a_k_in);
                    ldm_x4(ah[mt], abase + OF_A + row * APITCH + col * 2);
                }
#pragma unroll
                for (int p = 0; p < 4; p++) {
                    uint32_t nrow = (uint32_t)(nw * 64 + p * 16 + b_n_in);
                    uint32_t col = (uint32_t)(k0 + b_k_in);
                    uint32_t bh[4];
                    ldm_x4(bh, abase + OF_B + nrow * APITCH + col * 2);
#pragma unroll
                    for (int mt = 0; mt < 2; mt++) {
#pragma unroll
                        for (int half = 0; half < 2; half++) {
                            mma_f16(acc[mt][p * 2 + half], ah[mt], bh + half * 2);
                        }
                    }
                }
            }
            if (c < 3) {
                storeA(st, nxt, bm, c + 1);  // convert tail (+ x16 stream-out)
                CP_WAIT0();                  // B(c+1) landed
            }
            __syncthreads();
        }

        // ---- epilogue: s = sum_n w2[n]*tanh(h + b1[n]) + b2 ----
        float part[2][2] = {{0.f, 0.f}, {0.f, 0.f}};
#pragma unroll
        for (int mt = 0; mt < 2; mt++) {
#pragma unroll
            for (int nt = 0; nt < 8; nt++) {
                int col0 = nw * 64 + nt * 8 + (lane & 3) * 2;
                float w0 = __ldg(w2 + col0), w1v = __ldg(w2 + col0 + 1);
                float c0 = __ldg(b1 + col0), c1 = __ldg(b1 + col0 + 1);
                const float* d = acc[mt][nt];
                part[mt][0] += w0 * tanh_hw(d[0] + c0) + w1v * tanh_hw(d[1] + c1);
                part[mt][1] += w0 * tanh_hw(d[2] + c0) + w1v * tanh_hw(d[3] + c1);
            }
        }
#pragma unroll
        for (int mt = 0; mt < 2; mt++)
#pragma unroll
            for (int h = 0; h < 2; h++) {
                part[mt][h] += __shfl_xor_sync(0xFFFFFFFF, part[mt][h], 1);
                part[mt][h] += __shfl_xor_sync(0xFFFFFFFF, part[mt][h], 2);
            }
        float* red = (float*)(smem + OF_RED);     // [64][4], dedicated region
        if ((lane & 3) == 0) {
#pragma unroll
            for (int mt = 0; mt < 2; mt++)
#pragma unroll
                for (int h = 0; h < 2; h++) {
                    int rowl = mw * 32 + mt * 16 + h * 8 + (lane >> 2);
                    red[rowl * 4 + nw] = part[mt][h];
                }
        }
        __syncthreads();
        if (tid < 64) {
            float v = red[tid * 4] + red[tid * 4 + 1] + red[tid * 4 + 2] +
                      red[tid * 4 + 3];
            g_s[bm + tid] = v + b2v;
        }
        if (has_next) {
            storeA(st, 0, ntile * 64, 0);        // next tile chunk 0 -> buf 0
            CP_WAIT0();
        }
        __syncthreads();
    }
}

// ---------------- fused segment softmax + pooling (1 block / segment) -------
// No max-shift needed: scores are tanh-bounded, exp cannot overflow fp32.
#define ESCAP 2048
__global__ __launch_bounds__(256)
void pool2_kernel(const void* batch) {
    __shared__ float es[ESCAP];
    __shared__ float red[8];
    __shared__ float2 comb[128];
    __shared__ int bounds[2];
    const int seg = blockIdx.x;
    const int tid = threadIdx.x;
    const int is64 = g_is64;

    if (tid < 2) {                                 // binary search bounds
        int target = seg + tid;
        int lo = 0, hi = NR;
        while (lo < hi) {
            int mid = (lo + hi) >> 1;
            if (getb(batch, mid, is64) < target) lo = mid + 1; else hi = mid;
        }
        bounds[tid] = lo;
    }
    __syncthreads();
    const int lo = bounds[0], hi = bounds[1];
    const int cnt = hi - lo;
    if (cnt <= 0) { g_pooled[(size_t)seg * DD + tid] = 0.f; return; }
    const bool fit = (cnt <= ESCAP);

    // phase 1: exp + segment sum
    float s = 0.f;
    for (int r = lo + tid; r < hi; r += 256) {
        float e = __expf(g_s[r]);
        if (fit) es[r - lo] = e;
        s += e;
    }
#pragma unroll
    for (int o = 16; o; o >>= 1) s += __shfl_xor_sync(0xFFFFFFFFu, s, o);
    if ((tid & 31) == 0) red[tid >> 5] = s;
    __syncthreads();
    if (tid == 0) {
        float t = 0.f;
#pragma unroll
        for (int i = 0; i < 8; i++) t += red[i];
        red[0] = t;
    }
    __syncthreads();
    const float inv = 1.f / red[0];

    // phase 2: acc[col] = sum_r e_r * x16[r][col]; pooled = acc * inv
    if (fit) {
        const int half_id = tid >> 7;             // 0: even rows, 1: odd rows
        const int cp = tid & 127;                 // col pair (2cp, 2cp+1)
        float ax = 0.f, ay = 0.f;
        const uint32_t* xp = (const uint32_t*)g_x16 + (size_t)lo * 128 + cp;
        int r = half_id;
        for (; r + 6 < cnt; r += 8) {
            uint32_t u0 = xp[(size_t)r * 128];
            uint32_t u1 = xp[(size_t)(r + 2) * 128];
            uint32_t u2 = xp[(size_t)(r + 4) * 128];
            uint32_t u3 = xp[(size_t)(r + 6) * 128];
            float2 f0 = __half22float2(*(__half2*)&u0);
            float2 f1 = __half22float2(*(__half2*)&u1);
            float2 f2 = __half22float2(*(__half2*)&u2);
            float2 f3 = __half22float2(*(__half2*)&u3);
            float e0 = es[r], e1 = es[r + 2], e2 = es[r + 4], e3 = es[r + 6];
            ax += e0 * f0.x + e1 * f1.x + e2 * f2.x + e3 * f3.x;
            ay += e0 * f0.y + e1 * f1.y + e2 * f2.y + e3 * f3.y;
        }
        for (; r < cnt; r += 2) {
            uint32_t u = xp[(size_t)r * 128];
            float2 f = __half22float2(*(__half2*)&u);
            ax += es[r] * f.x;
            ay += es[r] * f.y;
        }
        __syncthreads();
        if (half_id == 1) comb[cp] = make_float2(ax, ay);
        __syncthreads();
        if (half_id == 0) {
            float2 o = comb[cp];
            float2 outv = make_float2((ax + o.x) * inv, (ay + o.y) * inv);
            *(float2*)&g_pooled[(size_t)seg * DD + 2 * cp] = outv;
        }
    } else {
        float a0 = 0.f;
        const __half* xp = g_x16 + (size_t)lo * DD + tid;
        for (int r = 0; r < cnt; r++)
            a0 += __expf(g_s[lo + r]) * __half2float(xp[(size_t)r * DD]);
        g_pooled[(size_t)seg * DD + tid] = a0 * inv;
    }
}

// ---------------- output GEMM: out = pooled @ Wp + bp ----------------------
__global__ void out_kernel(const float* __restrict__ Wp,
                           const float* __restrict__ bp,
                           float* __restrict__ out) {
    __shared__ float Ps[16][256];
    const int row0 = blockIdx.x * 16;
    const int tid = threadIdx.x;
    for (int idx = tid; idx < 16 * 256; idx += 256)
        (&Ps[0][0])[idx] = g_pooled[(size_t)row0 * DD + idx];
    __syncthreads();
    float acc[16];
#pragma unroll
    for (int r = 0; r < 16; r++) acc[r] = 0.f;
    const int col = tid;
    for (int k = 0; k < 256; k++) {
        float w = Wp[(size_t)k * DD + col];
#pragma unroll
        for (int r = 0; r < 16; r++) acc[r] += Ps[r][k] * w;
    }
    const float bb = bp[col];
#pragma unroll
    for (int r = 0; r < 16; r++)
        out[(size_t)(row0 + r) * DD + col] = acc[r] + bb;
}

// ---------------- launch ----------------------------------------------------
extern "C" void kernel_launch(void* const* d_in, const int* in_sizes, int n_in,
                              void* d_out, int out_size) {
    const float* x  = (const float*)d_in[0];
    const void*  bt = d_in[1];
    const float* W1 = (const float*)d_in[2];
    const float* b1 = (const float*)d_in[3];
    const float* w2 = (const float*)d_in[4];
    const float* b2 = (const float*)d_in[5];
    const float* Wp = (const float*)d_in[6];
    const float* bp = (const float*)d_in[7];
    float* out = (float*)d_out;

    cudaFuncSetAttribute(score_mma_kernel,
                         cudaFuncAttributeMaxDynamicSharedMemorySize, SC_SMEM);

    int dev = 0, sms = 148;
    cudaGetDevice(&dev);
    cudaDeviceGetAttribute(&sms, cudaDevAttrMultiProcessorCount, dev);
    int score_grid = 2 * sms;                      // exactly resident (2/SM)
    if (score_grid > NTILES) score_grid = NTILES;

    init_kernel<<<1, 32>>>(bt);
    prep_w1_kernel<<<(DD * DD + 255) / 256, 256>>>(W1);
    dummy_kernel<<<1, 32>>>();   // keeps score at 4th launch (ncu window)
    score_mma_kernel<<<score_grid, 256, SC_SMEM>>>(x, b1, w2, b2);
    pool2_kernel<<<BS, 256>>>(bt);
    out_kernel<<<BS / 16, 256>>>(Wp, bp, out);
}

// round 17
// speedup vs baseline: 1.4990x; 1.4990x over previous
#include <cuda_runtime.h>
#include <cuda_fp16.h>
#include <math.h>
#include <stdint.h>

#define NR 1000000
#define DD 256
#define BS 4096

// ---------------- scratch (device globals: no allocations allowed) ----------
__device__ float g_s[NR];          // raw scores
__device__ float g_pooled[BS * DD];
__device__ int   g_is64;           // batch dtype flag: 1 = int64, 0 = int32
// W1 as fp16, transposed to [n][k] (K contiguous per output column)
__device__ __align__(16) __half g_Bh16[DD * DD];
// x converted to fp16 by score kernel (side product); read by pool2
__device__ __align__(16) __half g_x16[(size_t)NR * DD];

__device__ __forceinline__ int getb(const void* p, int i, int is64) {
    if (is64) return (int)((const long long*)p)[i];
    return ((const int*)p)[i];
}

__device__ __forceinline__ uint32_t smem_u32(const void* p) {
    uint32_t a;
    asm("{ .reg .u64 t; cvta.to.shared.u64 t, %1; cvt.u32.u64 %0, t; }"
        : "=r"(a) : "l"(p));
    return a;
}
__device__ __forceinline__ void ldm_x4(uint32_t* r, uint32_t addr) {
    asm volatile("ldmatrix.sync.aligned.m8n8.x4.shared.b16 {%0,%1,%2,%3}, [%4];"
        : "=r"(r[0]), "=r"(r[1]), "=r"(r[2]), "=r"(r[3]) : "r"(addr));
}
__device__ __forceinline__ void mma_f16(float* d, const uint32_t* a,
                                        const uint32_t* b) {
    asm volatile(
        "mma.sync.aligned.m16n8k16.row.col.f32.f16.f16.f32 "
        "{%0,%1,%2,%3}, {%4,%5,%6,%7}, {%8,%9}, {%0,%1,%2,%3};"
        : "+f"(d[0]), "+f"(d[1]), "+f"(d[2]), "+f"(d[3])
        : "r"(a[0]), "r"(a[1]), "r"(a[2]), "r"(a[3]), "r"(b[0]), "r"(b[1]));
}
__device__ __forceinline__ void cpasync16(uint32_t dst, const void* src) {
    asm volatile("cp.async.cg.shared.global [%0], [%1], 16;"
                 :: "r"(dst), "l"(src) : "memory");
}
#define CP_COMMIT() asm volatile("cp.async.commit_group;" ::: "memory")
#define CP_WAIT0()  asm volatile("cp.async.wait_group 0;" ::: "memory")

// HW tanh approximation (MUFU.TANH, sm_75+)
__device__ __forceinline__ float tanh_hw(float v) {
    float r;
    asm("tanh.approx.f32 %0, %1;" : "=f"(r) : "f"(v));
    return r;
}

// ---------------- init: detect batch dtype only -----------------------------
__global__ void init_kernel(const void* batch) {
    if (threadIdx.x == 0 && blockIdx.x == 0) {
        long long v = ((const long long*)batch)[NR / 2 - 1];
        g_is64 = (v >= 0 && v < BS) ? 1 : 0;
    }
}

// ---------------- prep: W1 -> fp16, transpose to [n][k] ---------------------
__global__ void prep_w1_kernel(const float* __restrict__ W1) {
    int i = blockIdx.x * blockDim.x + threadIdx.x;
    if (i >= DD * DD) return;
    int k = i >> 8, n = i & 255;                     // W1[k][n]
    g_Bh16[n * DD + k] = __float2half_rn(W1[i]);
}

// ---------------- dummy: keeps score at 4th launch (ncu window) -------------
__global__ void dummy_kernel() {}

// ---------------- score GEMM: single-pass fp16, 2 CTAs/SM (R15 config) ------
// CTA: 256 threads = 8 warps (2 M x 4 N). Tile M=64, N=256, K chunks of 64.
// Static addressing throughout (runtime-variant inner addressing regressed
// in R14 and R16 -- do not reintroduce).
#define APITCH 144
#define BUFSZ  46080
#define OF_A   0
#define OF_B   9216
#define SC_SMEM (2 * BUFSZ)
__global__ __launch_bounds__(256, 2)
void score_mma_kernel(const float* __restrict__ x, const float* __restrict__ b1,
                      const float* __restrict__ w2, const float* __restrict__ b2p) {
    extern __shared__ char smem[];
    const uint32_t sb = smem_u32(smem);
    const int tid = threadIdx.x;
    const int wid = tid >> 5, lane = tid & 31;
    const int mw = wid & 1;          // M warp: rows mw*32 .. +31
    const int nw = wid >> 1;         // N warp: cols nw*64 .. +63
    const int bm = blockIdx.x * 64;

    float acc[2][8][4];
#pragma unroll
    for (int a = 0; a < 2; a++)
#pragma unroll
        for (int b = 0; b < 8; b++)
#pragma unroll
            for (int c = 0; c < 4; c++) acc[a][b][c] = 0.f;

    const int a_row_in = (lane & 15);
    const int a_k_in   = (lane & 16) >> 1;
    const int b_n_in   = (lane & 7) + ((lane & 16) >> 1);
    const int b_k_in   = (lane & 8);

    auto loadB = [&](int c, int buf) {
        uint32_t base = sb + buf * BUFSZ;
#pragma unroll
        for (int t = 0; t < 8; t++) {
            int idx = tid + t * 256;             // 0..2047
            int n = idx >> 3, q = idx & 7;
            uint32_t doff = (uint32_t)n * APITCH + (uint32_t)q * 16;
            size_t gsrc = (size_t)n * DD + c * 64 + q * 8;
            cpasync16(base + OF_B + doff, g_Bh16 + gsrc);
        }
        CP_COMMIT();
    };
    auto loadA = [&](int c, float4* st) {
#pragma unroll
        for (int t = 0; t < 4; t++) {
            int idx = tid + t * 256;             // 0..1023 float4s
            int r = idx >> 4, q = idx & 15;
            st[t] = *(const float4*)(x + (size_t)(bm + r) * DD + c * 64 + q * 4);
        }
    };
    // stores chunk c to smem buf AND streams fp16 values to g_x16 (evict-first)
    auto storeA = [&](const float4* st, int buf, int c) {
        char* base = smem + buf * BUFSZ;
#pragma unroll
        for (int t = 0; t < 4; t++) {
            int idx = tid + t * 256;
            int r = idx >> 4, q = idx & 15;
            __half2 h0 = __floats2half2_rn(st[t].x, st[t].y);
            __half2 h1 = __floats2half2_rn(st[t].z, st[t].w);
            uint2 hp = make_uint2(*(uint32_t*)&h0, *(uint32_t*)&h1);
            uint32_t off = (uint32_t)r * APITCH + (uint32_t)q * 8;
            *(uint2*)(base + OF_A + off) = hp;
            __stcs((uint2*)(g_x16 + (size_t)(bm + r) * DD + c * 64 + q * 4), hp);
        }
    };

    // ---- prologue: fill buffer 0 ----
    float4 st[4];
    loadB(0, 0);
    loadA(0, st);
    storeA(st, 0, 0);
    CP_WAIT0();
    __syncthreads();

#pragma unroll 1
    for (int c = 0; c < 4; c++) {
        const int cur = c & 1, nxt = cur ^ 1;
        if (c < 3) {
            loadB(c + 1, nxt);       // cp.async overlaps MMA burst
            loadA(c + 1, st);        // LDG latency hidden under MMA burst
        }
        // ---- compute on buf[cur]: 4 k16 steps (static order) ----
        const uint32_t abase = sb + (uint32_t)cur * BUFSZ;
#pragma unroll
        for (int ks = 0; ks < 4; ks++) {
            const int k0 = ks * 16;
            uint32_t ah[2][4];
#pragma unroll
            for (int mt = 0; mt < 2; mt++) {
                uint32_t row = (uint32_t)(mw * 32 + mt * 16 + a_row_in);
                uint32_t col = (uint32_t)(k0 + a_k_in);
                ldm_x4(ah[mt], abase + OF_A + row * APITCH + col * 2);
            }
#pragma unroll
            for (int p = 0; p < 4; p++) {
                uint32_t nrow = (uint32_t)(nw * 64 + p * 16 + b_n_in);
                uint32_t col = (uint32_t)(k0 + b_k_in);
                uint32_t bh[4];
                ldm_x4(bh, abase + OF_B + nrow * APITCH + col * 2);
#pragma unroll
                for (int mt = 0; mt < 2; mt++) {
#pragma unroll
                    for (int half = 0; half < 2; half++) {
                        mma_f16(acc[mt][p * 2 + half], ah[mt], bh + half * 2);
                    }
                }
            }
        }
        if (c < 3) {
            storeA(st, nxt, c + 1);  // short convert tail (+ x16 stream-out)
            CP_WAIT0();              // B(c+1) landed
        }
        __syncthreads();
    }

    // ---- epilogue: s = sum_n w2[n]*tanh(h + b1[n]) + b2 ----
    float part[2][2] = {{0.f, 0.f}, {0.f, 0.f}};
#pragma unroll
    for (int mt = 0; mt < 2; mt++) {
#pragma unroll
        for (int nt = 0; nt < 8; nt++) {
            int col0 = nw * 64 + nt * 8 + (lane & 3) * 2;
            float w0 = __ldg(w2 + col0), w1v = __ldg(w2 + col0 + 1);
            float c0 = __ldg(b1 + col0), c1 = __ldg(b1 + col0 + 1);
            const float* d = acc[mt][nt];
            part[mt][0] += w0 * tanh_hw(d[0] + c0) + w1v * tanh_hw(d[1] + c1);
            part[mt][1] += w0 * tanh_hw(d[2] + c0) + w1v * tanh_hw(d[3] + c1);
        }
    }
#pragma unroll
    for (int mt = 0; mt < 2; mt++)
#pragma unroll
        for (int h = 0; h < 2; h++) {
            part[mt][h] += __shfl_xor_sync(0xFFFFFFFF, part[mt][h], 1);
            part[mt][h] += __shfl_xor_sync(0xFFFFFFFF, part[mt][h], 2);
        }
    __syncthreads();
    float* red = (float*)smem;                    // [64][4]
    if ((lane & 3) == 0) {
#pragma unroll
        for (int mt = 0; mt < 2; mt++)
#pragma unroll
            for (int h = 0; h < 2; h++) {
                int rowl = mw * 32 + mt * 16 + h * 8 + (lane >> 2);
                red[rowl * 4 + nw] = part[mt][h];
            }
    }
    __syncthreads();
    if (tid < 64) {
        float v = red[tid * 4] + red[tid * 4 + 1] + red[tid * 4 + 2] +
                  red[tid * 4 + 3];
        g_s[bm + tid] = v + __ldg(b2p);
    }
}

// ---------------- fused segment softmax + pooling (1 block / segment) -------
// No max-shift needed (tanh-bounded scores). Phase 2 uses uint2 (8B) loads:
// 4 row-groups of 64 threads, each thread owns 4 columns; 4 loads in flight.
#define ESCAP 2048
__global__ __launch_bounds__(256)
void pool2_kernel(const void* batch) {
    __shared__ float es[ESCAP];
    __shared__ float red[8];
    __shared__ float4 comb4[3][64];
    __shared__ int bounds[2];
    const int seg = blockIdx.x;
    const int tid = threadIdx.x;
    const int is64 = g_is64;

    if (tid < 2) {                                 // binary search bounds
        int target = seg + tid;
        int lo = 0, hi = NR;
        while (lo < hi) {
            int mid = (lo + hi) >> 1;
            if (getb(batch, mid, is64) < target) lo = mid + 1; else hi = mid;
        }
        bounds[tid] = lo;
    }
    __syncthreads();
    const int lo = bounds[0], hi = bounds[1];
    const int cnt = hi - lo;
    if (cnt <= 0) { g_pooled[(size_t)seg * DD + tid] = 0.f; return; }
    const bool fit = (cnt <= ESCAP);

    // phase 1: exp + segment sum
    float s = 0.f;
    for (int r = lo + tid; r < hi; r += 256) {
        float e = __expf(g_s[r]);
        if (fit) es[r - lo] = e;
        s += e;
    }
#pragma unroll
    for (int o = 16; o; o >>= 1) s += __shfl_xor_sync(0xFFFFFFFFu, s, o);
    if ((tid & 31) == 0) red[tid >> 5] = s;
    __syncthreads();
    if (tid == 0) {
        float t = 0.f;
#pragma unroll
        for (int i = 0; i < 8; i++) t += red[i];
        red[0] = t;
    }
    __syncthreads();
    const float inv = 1.f / red[0];

    // phase 2: acc[col] = sum_r e_r * x16[r][col]; pooled = acc * inv
    if (fit) {
        const int grp = tid >> 6;                 // row group: rows r%4 == grp
        const int cq = tid & 63;                  // col quad: cols 4cq..4cq+3
        float a0 = 0.f, a1 = 0.f, a2 = 0.f, a3 = 0.f;
        const uint2* xp = (const uint2*)g_x16 + (size_t)lo * 64 + cq;
        int r = grp;
        for (; r + 12 < cnt; r += 16) {           // 4 x 8B loads in flight
            uint2 u0 = xp[(size_t)r * 64];
            uint2 u1 = xp[(size_t)(r + 4) * 64];
            uint2 u2 = xp[(size_t)(r + 8) * 64];
            uint2 u3 = xp[(size_t)(r + 12) * 64];
            float2 p0 = __half22float2(*(__half2*)&u0.x);
            float2 q0 = __half22float2(*(__half2*)&u0.y);
            float2 p1 = __half22float2(*(__half2*)&u1.x);
            float2 q1 = __half22float2(*(__half2*)&u1.y);
            float2 p2 = __half22float2(*(__half2*)&u2.x);
            float2 q2 = __half22float2(*(__half2*)&u2.y);
            float2 p3 = __half22float2(*(__half2*)&u3.x);
            float2 q3 = __half22float2(*(__half2*)&u3.y);
            float e0 = es[r], e1 = es[r + 4], e2 = es[r + 8], e3 = es[r + 12];
            a0 += e0 * p0.x + e1 * p1.x + e2 * p2.x + e3 * p3.x;
            a1 += e0 * p0.y + e1 * p1.y + e2 * p2.y + e3 * p3.y;
            a2 += e0 * q0.x + e1 * q1.x + e2 * q2.x + e3 * q3.x;
            a3 += e0 * q0.y + e1 * q1.y + e2 * q2.y + e3 * q3.y;
        }
        for (; r < cnt; r += 4) {
            uint2 u = xp[(size_t)r * 64];
            float2 p = __half22float2(*(__half2*)&u.x);
            float2 q = __half22float2(*(__half2*)&u.y);
            float e = es[r];
            a0 += e * p.x; a1 += e * p.y; a2 += e * q.x; a3 += e * q.y;
        }
        __syncthreads();
        if (grp > 0) comb4[grp - 1][cq] = make_float4(a0, a1, a2, a3);
        __syncthreads();
        if (grp == 0) {
            float4 c1v = comb4[0][cq], c2v = comb4[1][cq], c3v = comb4[2][cq];
            float4 outv;
            outv.x = (a0 + c1v.x + c2v.x + c3v.x) * inv;
            outv.y = (a1 + c1v.y + c2v.y + c3v.y) * inv;
            outv.z = (a2 + c1v.z + c2v.z + c3v.z) * inv;
            outv.w = (a3 + c1v.w + c2v.w + c3v.w) * inv;
            *(float4*)&g_pooled[(size_t)seg * DD + 4 * cq] = outv;
        }
    } else {
        float a0 = 0.f;
        const __half* xp = g_x16 + (size_t)lo * DD + tid;
        for (int r = 0; r < cnt; r++)
            a0 += __expf(g_s[lo + r]) * __half2float(xp[(size_t)r * DD]);
        g_pooled[(size_t)seg * DD + tid] = a0 * inv;
    }
}

// ---------------- output GEMM: out = pooled @ Wp + bp ----------------------
__global__ void out_kernel(const float* __restrict__ Wp,
                           const float* __restrict__ bp,
                           float* __restrict__ out) {
    __shared__ float Ps[16][256];
    const int row0 = blockIdx.x * 16;
    const int tid = threadIdx.x;
    for (int idx = tid; idx < 16 * 256; idx += 256)
        (&Ps[0][0])[idx] = g_pooled[(size_t)row0 * DD + idx];
    __syncthreads();
    float acc[16];
#pragma unroll
    for (int r = 0; r < 16; r++) acc[r] = 0.f;
    const int col = tid;
    for (int k = 0; k < 256; k++) {
        float w = Wp[(size_t)k * DD + col];
#pragma unroll
        for (int r = 0; r < 16; r++) acc[r] += Ps[r][k] * w;
    }
    const float bb = bp[col];
#pragma unroll
    for (int r = 0; r < 16; r++)
        out[(size_t)(row0 + r) * DD + col] = acc[r] + bb;
}

// ---------------- launch ----------------------------------------------------
extern "C" void kernel_launch(void* const* d_in, const int* in_sizes, int n_in,
                              void* d_out, int out_size) {
    const float* x  = (const float*)d_in[0];
    const void*  bt = d_in[1];
    const float* W1 = (const float*)d_in[2];
    const float* b1 = (const float*)d_in[3];
    const float* w2 = (const float*)d_in[4];
    const float* b2 = (const float*)d_in[5];
    const float* Wp = (const float*)d_in[6];
    const float* bp = (const float*)d_in[7];
    float* out = (float*)d_out;

    cudaFuncSetAttribute(score_mma_kernel,
                         cudaFuncAttributeMaxDynamicSharedMemorySize, SC_SMEM);

    init_kernel<<<1, 32>>>(bt);
    prep_w1_kernel<<<(DD * DD + 255) / 256, 256>>>(W1);
    dummy_kernel<<<1, 32>>>();   // keeps score at 4th launch (ncu window)
    score_mma_kernel<<<NR / 64, 256, SC_SMEM>>>(x, b1, w2, b2);
    pool2_kernel<<<BS, 256>>>(bt);
    out_kernel<<<BS / 16, 256>>>(Wp, bp, out);
}